// round 16
// baseline (speedup 1.0000x reference)
#include <cuda_runtime.h>
#include <cuda_bf16.h>
#include <cuda_fp16.h>
#include <math.h>
#include <stdint.h>

// Problem constants
#define BB 2
#define SS 2048
#define DD 2048
#define HH 16
#define DH 128
#define MM (BB*SS)          // 4096
#define TRIO (3*DD)         // 6144
#define EPS 1e-6f

// Scratch (device globals; no allocation allowed)
__device__ float g_attn[(size_t)MM * DD];    // 33.6 MB
__device__ uint32_t g_qh[(size_t)BB*HH*SS*64];
__device__ uint32_t g_ql[(size_t)BB*HH*SS*64];
__device__ uint32_t g_kh[(size_t)BB*HH*SS*64];
__device__ uint32_t g_kl[(size_t)BB*HH*SS*64];
__device__ uint32_t g_vf[(size_t)BB*HH*DH*(SS/2)];
__device__ uint32_t g_xf[(size_t)MM*(DD/2)];
__device__ uint32_t g_wif[(size_t)TRIO*(DD/2)];
__device__ uint32_t g_wof[(size_t)DD*(DD/2)];
__device__ uint32_t g_af[(size_t)MM*(DD/2)];
// RoPE tables
__device__ float g_rc[(size_t)SS*64];
__device__ float g_rs[(size_t)SS*64];

// ---------------------------------------------------------------------------
// Helpers
// ---------------------------------------------------------------------------
__device__ __forceinline__ void cpasync16u(uint32_t* s, const uint32_t* g) {
    uint32_t sa = (uint32_t)__cvta_generic_to_shared(s);
    asm volatile("cp.async.cg.shared.global [%0], [%1], 16;" :: "r"(sa), "l"(g));
}
__device__ __forceinline__ void mma_bf16(float c[4], const uint32_t a[4], const uint32_t b[2]) {
    asm volatile(
        "mma.sync.aligned.m16n8k16.row.col.f32.bf16.bf16.f32 "
        "{%0,%1,%2,%3}, {%4,%5,%6,%7}, {%8,%9}, {%0,%1,%2,%3};"
        : "+f"(c[0]), "+f"(c[1]), "+f"(c[2]), "+f"(c[3])
        : "r"(a[0]), "r"(a[1]), "r"(a[2]), "r"(a[3]), "r"(b[0]), "r"(b[1]));
}
__device__ __forceinline__ void mma_f16(float c[4], const uint32_t a[4], const uint32_t b[2]) {
    asm volatile(
        "mma.sync.aligned.m16n8k16.row.col.f32.f16.f16.f32 "
        "{%0,%1,%2,%3}, {%4,%5,%6,%7}, {%8,%9}, {%0,%1,%2,%3};"
        : "+f"(c[0]), "+f"(c[1]), "+f"(c[2]), "+f"(c[3])
        : "r"(a[0]), "r"(a[1]), "r"(a[2]), "r"(a[3]), "r"(b[0]), "r"(b[1]));
}
__device__ __forceinline__ void ldm_x4(uint32_t d[4], uint32_t saddr) {
    asm volatile("ldmatrix.sync.aligned.m8n8.x4.shared.b16 {%0,%1,%2,%3}, [%4];"
        : "=r"(d[0]), "=r"(d[1]), "=r"(d[2]), "=r"(d[3]) : "r"(saddr));
}
__device__ __forceinline__ void splitbf(float x0, float x1, uint32_t& hi, uint32_t& lo) {
    __nv_bfloat162 hp = __floats2bfloat162_rn(x0, x1);
    float r0 = x0 - __bfloat162float(hp.x);
    float r1 = x1 - __bfloat162float(hp.y);
    __nv_bfloat162 lp = __floats2bfloat162_rn(r0, r1);
    hi = *reinterpret_cast<uint32_t*>(&hp);
    lo = *reinterpret_cast<uint32_t*>(&lp);
}
__device__ __forceinline__ uint32_t packf16(float x0, float x1) {
    __half2 hp = __floats2half2_rn(x0, x1);
    return *reinterpret_cast<uint32_t*>(&hp);
}
__device__ __forceinline__ int xsw(int r, int p, int rowu) {
    return r*rowu + ((((p >> 2) ^ (r & 7)) << 2) | (p & 3));
}

// ---------------------------------------------------------------------------
// RoPE cos/sin table precompute. One thread per (s, pair).
// ---------------------------------------------------------------------------
__global__ __launch_bounds__(256) void rope_tab(const float* __restrict__ rp)
{
    const int i = blockIdx.x * 256 + threadIdx.x;     // 0 .. SS*64-1
    const float a = rp[i];
    g_rc[i] = cosf(a);
    g_rs[i] = sinf(a);
}

// ---------------------------------------------------------------------------
// fp32 -> packed fp16x2 plane. One thread per float4.
// ---------------------------------------------------------------------------
__global__ __launch_bounds__(256) void split_plane_f16(
    const float* __restrict__ src, uint32_t* __restrict__ pf)
{
    const size_t i = (size_t)blockIdx.x * 256 + threadIdx.x;
    const float4 v = *(const float4*)(src + i*4);
    pf[2*i]     = packf16(v.x, v.y);
    pf[2*i + 1] = packf16(v.z, v.w);
}

#define GKU 32                 // u32 per row per k-tile
#define GBUF (128*GKU*2)       // A + B per buffer = 8192 u32 (32 KB)

// ---------------------------------------------------------------------------
// QKV GEMM with FUSED epilogue (RoPE via tables).
// ---------------------------------------------------------------------------
__global__ __launch_bounds__(256, 2) void f16_gemm_qkv_fused(
    const uint32_t* __restrict__ A, const uint32_t* __restrict__ B,
    const float* __restrict__ bias, const float* __restrict__ qk_w)
{
    extern __shared__ uint32_t sm[];
    const uint32_t sbase = (uint32_t)__cvta_generic_to_shared(sm);
    const int Ku = DD/2;

    const int tid = threadIdx.x;
    const int bm0 = blockIdx.y * 128;
    const int bn0 = blockIdx.x * 128;
    const int warp = tid >> 5, lane = tid & 31;
    const int wm0 = (warp >> 2) * 64;
    const int wn0 = (warp & 3) * 32;
    const int qr = lane >> 2, qc = lane & 3;
    const int lt15 = lane & 15, lt7 = lane & 7;
    const int asel = lane >> 4;
    const int brow = lane >> 4;
    const int bsel = (lane >> 3) & 1;

    const int lr = tid >> 3;
    const int lg = tid & 7;
    const uint32_t* Agp = A + (size_t)(bm0 + lr) * Ku + lg*4;
    const uint32_t* Bgp = B + (size_t)(bn0 + lr) * Ku + lg*4;
    const size_t rstep = (size_t)32 * Ku;
    int dsts[4];
    #pragma unroll
    for (int rep = 0; rep < 4; rep++) {
        const int r = lr + rep*32;
        dsts[rep] = r*32 + ((lg ^ (r & 7)) << 2);
    }

    float acc[4][4][4];
    #pragma unroll
    for (int i = 0; i < 4; i++)
        #pragma unroll
        for (int j = 0; j < 4; j++)
            #pragma unroll
            for (int u = 0; u < 4; u++) acc[i][j][u] = 0.f;

    const int nk = Ku / GKU;

    #pragma unroll
    for (int rep = 0; rep < 4; rep++) {
        cpasync16u(sm + dsts[rep],             Agp + rep*rstep);
        cpasync16u(sm + 4096 + dsts[rep],      Bgp + rep*rstep);
    }
    asm volatile("cp.async.commit_group;\n");

    for (int kt = 0; kt < nk; kt++) {
        if (kt + 1 < nk) {
            uint32_t* Bn = sm + ((kt + 1) & 1) * GBUF;
            const int ko = (kt + 1) * GKU;
            #pragma unroll
            for (int rep = 0; rep < 4; rep++) {
                cpasync16u(Bn + dsts[rep],        Agp + ko + rep*rstep);
                cpasync16u(Bn + 4096 + dsts[rep], Bgp + ko + rep*rstep);
            }
            asm volatile("cp.async.commit_group;\n");
            asm volatile("cp.async.wait_group 1;\n");
        } else {
            asm volatile("cp.async.wait_group 0;\n");
        }
        __syncthreads();

        const uint32_t abuf = sbase + ((kt & 1) * GBUF) * 4;
        const uint32_t bbuf = abuf + 4096 * 4;

        #pragma unroll
        for (int ch = 0; ch < 4; ch++) {
            uint32_t af[4][4];
            #pragma unroll
            for (int im = 0; im < 4; im++) {
                const int row = wm0 + im*16 + lt15;
                const int gr  = 2*ch + asel;
                ldm_x4(af[im], abuf + 4*(row*32 + ((gr ^ (row & 7)) << 2)));
            }
            uint32_t bf[2][4];
            #pragma unroll
            for (int ip = 0; ip < 2; ip++) {
                const int nrow = wn0 + (ip*2 + brow)*8 + lt7;
                const int gr = 2*ch + bsel;
                ldm_x4(bf[ip], bbuf + 4*(nrow*32 + ((gr ^ (nrow & 7)) << 2)));
            }
            #pragma unroll
            for (int in = 0; in < 4; in++) {
                uint32_t bb[2] = { bf[in>>1][(in&1)*2], bf[in>>1][(in&1)*2 + 1] };
                #pragma unroll
                for (int im = 0; im < 4; im++)
                    mma_f16(acc[im][in], af[im], bb);
            }
        }
        __syncthreads();
    }

    // ------------------- fused epilogue -------------------
    const int which = bn0 >> 11;          // 0=q, 1=k, 2=v
    const int hh = (bn0 >> 7) & 15;
    const int bb2 = bm0 >> 11;
    const int s0 = bm0 & (SS - 1);

    if (which < 2) {
        float* buf = (float*)sm;          // [4][128] row sums
        float ssum[4][2];
        #pragma unroll
        for (int im = 0; im < 4; im++) {
            #pragma unroll
            for (int rr = 0; rr < 2; rr++) {
                const int rl = wm0 + im*16 + qr + rr*8;
                const int s = s0 + rl;
                float a2 = 0.f;
                #pragma unroll
                for (int in = 0; in < 4; in++) {
                    const int c0 = wn0 + in*8 + qc*2;
                    const float cs = g_rc[s*64 + (c0 >> 1)];
                    const float sn = g_rs[s*64 + (c0 >> 1)];
                    const float x0 = acc[im][in][rr*2+0] + bias[bn0 + c0];
                    const float x1 = acc[im][in][rr*2+1] + bias[bn0 + c0 + 1];
                    const float y0 = x0*cs - x1*sn;
                    const float y1 = x0*sn + x1*cs;
                    acc[im][in][rr*2+0] = y0;
                    acc[im][in][rr*2+1] = y1;
                    a2 += y0*y0 + y1*y1;
                }
                ssum[im][rr] = a2;
            }
        }
        #pragma unroll
        for (int im = 0; im < 4; im++)
            #pragma unroll
            for (int rr = 0; rr < 2; rr++) {
                float v = ssum[im][rr];
                v += __shfl_xor_sync(0xffffffffu, v, 1);
                v += __shfl_xor_sync(0xffffffffu, v, 2);
                ssum[im][rr] = v;
            }
        const int wn_idx = warp & 3;
        if (qc == 0) {
            #pragma unroll
            for (int im = 0; im < 4; im++)
                #pragma unroll
                for (int rr = 0; rr < 2; rr++)
                    buf[wn_idx*128 + wm0 + im*16 + qr + rr*8] = ssum[im][rr];
        }
        __syncthreads();

        uint32_t* ph = which ? g_kh : g_qh;
        uint32_t* pl = which ? g_kl : g_ql;
        const size_t pbase = (size_t)(bb2*HH + hh) * SS * 64;
        #pragma unroll
        for (int im = 0; im < 4; im++) {
            #pragma unroll
            for (int rr = 0; rr < 2; rr++) {
                const int rl = wm0 + im*16 + qr + rr*8;
                const float tot = buf[rl] + buf[128 + rl] + buf[256 + rl] + buf[384 + rl];
                const float inv = rsqrtf(tot * (1.0f/DH) + EPS);
                const size_t rowb = pbase + (size_t)(s0 + rl) * 64;
                #pragma unroll
                for (int in = 0; in < 4; in++) {
                    const int c0 = wn0 + in*8 + qc*2;
                    const float o0 = acc[im][in][rr*2+0] * inv * qk_w[c0];
                    const float o1 = acc[im][in][rr*2+1] * inv * qk_w[c0+1];
                    uint32_t hi, lo;
                    splitbf(o0, o1, hi, lo);
                    ph[rowb + (c0 >> 1)] = hi;
                    pl[rowb + (c0 >> 1)] = lo;
                }
            }
        }
    } else {
        __half* vh = (__half*)g_vf;
        const size_t vb = (size_t)(bb2*HH + hh) * DH * SS;
        #pragma unroll
        for (int im = 0; im < 4; im++) {
            #pragma unroll
            for (int in = 0; in < 4; in++) {
                const int c0 = wn0 + in*8 + qc*2;
                #pragma unroll
                for (int rr = 0; rr < 2; rr++) {
                    const int s = s0 + wm0 + im*16 + qr + rr*8;
                    const float o0 = acc[im][in][rr*2+0] + bias[bn0 + c0];
                    const float o1 = acc[im][in][rr*2+1] + bias[bn0 + c0 + 1];
                    vh[vb + (size_t)c0*SS + s]       = __float2half_rn(o0);
                    vh[vb + (size_t)(c0+1)*SS + s]   = __float2half_rn(o1);
                }
            }
        }
    }
}

// ---------------------------------------------------------------------------
// Plain single-product fp16 GEMM (out-projection).
// ---------------------------------------------------------------------------
__global__ __launch_bounds__(256, 2) void f16_gemm_nt_bias(
    const uint32_t* __restrict__ A, const uint32_t* __restrict__ B,
    const float* __restrict__ bias, float* __restrict__ C,
    int M, int N, int Ku)
{
    extern __shared__ uint32_t sm[];
    const uint32_t sbase = (uint32_t)__cvta_generic_to_shared(sm);

    const int tid = threadIdx.x;
    const int bm0 = blockIdx.y * 128;
    const int bn0 = blockIdx.x * 128;
    const int warp = tid >> 5, lane = tid & 31;
    const int wm0 = (warp >> 2) * 64;
    const int wn0 = (warp & 3) * 32;
    const int qr = lane >> 2, qc = lane & 3;
    const int lt15 = lane & 15, lt7 = lane & 7;
    const int asel = lane >> 4;
    const int brow = lane >> 4;
    const int bsel = (lane >> 3) & 1;

    const int lr = tid >> 3;
    const int lg = tid & 7;
    const uint32_t* Agp = A + (size_t)(bm0 + lr) * Ku + lg*4;
    const uint32_t* Bgp = B + (size_t)(bn0 + lr) * Ku + lg*4;
    const size_t rstep = (size_t)32 * Ku;
    int dsts[4];
    #pragma unroll
    for (int rep = 0; rep < 4; rep++) {
        const int r = lr + rep*32;
        dsts[rep] = r*32 + ((lg ^ (r & 7)) << 2);
    }

    float acc[4][4][4];
    #pragma unroll
    for (int i = 0; i < 4; i++)
        #pragma unroll
        for (int j = 0; j < 4; j++)
            #pragma unroll
            for (int u = 0; u < 4; u++) acc[i][j][u] = 0.f;

    const int nk = Ku / GKU;

    #pragma unroll
    for (int rep = 0; rep < 4; rep++) {
        cpasync16u(sm + dsts[rep],             Agp + rep*rstep);
        cpasync16u(sm + 4096 + dsts[rep],      Bgp + rep*rstep);
    }
    asm volatile("cp.async.commit_group;\n");

    for (int kt = 0; kt < nk; kt++) {
        if (kt + 1 < nk) {
            uint32_t* Bn = sm + ((kt + 1) & 1) * GBUF;
            const int ko = (kt + 1) * GKU;
            #pragma unroll
            for (int rep = 0; rep < 4; rep++) {
                cpasync16u(Bn + dsts[rep],        Agp + ko + rep*rstep);
                cpasync16u(Bn + 4096 + dsts[rep], Bgp + ko + rep*rstep);
            }
            asm volatile("cp.async.commit_group;\n");
            asm volatile("cp.async.wait_group 1;\n");
        } else {
            asm volatile("cp.async.wait_group 0;\n");
        }
        __syncthreads();

        const uint32_t abuf = sbase + ((kt & 1) * GBUF) * 4;
        const uint32_t bbuf = abuf + 4096 * 4;

        #pragma unroll
        for (int ch = 0; ch < 4; ch++) {
            uint32_t af[4][4];
            #pragma unroll
            for (int im = 0; im < 4; im++) {
                const int row = wm0 + im*16 + lt15;
                const int gr  = 2*ch + asel;
                ldm_x4(af[im], abuf + 4*(row*32 + ((gr ^ (row & 7)) << 2)));
            }
            uint32_t bf[2][4];
            #pragma unroll
            for (int ip = 0; ip < 2; ip++) {
                const int nrow = wn0 + (ip*2 + brow)*8 + lt7;
                const int gr = 2*ch + bsel;
                ldm_x4(bf[ip], bbuf + 4*(nrow*32 + ((gr ^ (nrow & 7)) << 2)));
            }
            #pragma unroll
            for (int in = 0; in < 4; in++) {
                uint32_t bb[2] = { bf[in>>1][(in&1)*2], bf[in>>1][(in&1)*2 + 1] };
                #pragma unroll
                for (int im = 0; im < 4; im++)
                    mma_f16(acc[im][in], af[im], bb);
            }
        }
        __syncthreads();
    }

    #pragma unroll
    for (int im = 0; im < 4; im++) {
        #pragma unroll
        for (int in = 0; in < 4; in++) {
            const int r0 = bm0 + wm0 + im*16 + qr;
            const int c0 = bn0 + wn0 + in*8 + qc*2;
            const float2 b2 = *(const float2*)(bias + c0);
            float2 v;
            v.x = acc[im][in][0] + b2.x; v.y = acc[im][in][1] + b2.y;
            *(float2*)(C + (size_t)r0 * N + c0) = v;
            v.x = acc[im][in][2] + b2.x; v.y = acc[im][in][3] + b2.y;
            *(float2*)(C + (size_t)(r0 + 8) * N + c0) = v;
        }
    }
}

// ---------------------------------------------------------------------------
// Flash attention v5: FQ=128 q rows/block, warp tile M=32 (4 strips x 2
// halves), 1 block/SM. S = bf16 3-product, PV = fp16 1-product, ldmatrix.
// ---------------------------------------------------------------------------
#define AQH 0
#define AQL 8192
#define AKH 16384
#define AKL 20480
#define AVH 24576               // 4096 u32 (128 d x 32 pairs)
#define APH 28672               // 4096 u32 (128 rows x 32 pairs)
#define ALRED 32768             // 256 floats
#define ASZ ((32768 + 256) * 4) // 132096 B
#define SHIFTC 11.32f

__global__ __launch_bounds__(256, 1) void flash_attn_v5()
{
    extern __shared__ uint32_t smu[];
    float* smf = reinterpret_cast<float*>(smu);
    const uint32_t sb = (uint32_t)__cvta_generic_to_shared(smu);

    const int qb = (int)(gridDim.x - 1 - blockIdx.x);   // heavy first
    const int qm0 = qb * 128;
    const int h = blockIdx.y, b = blockIdx.z;
    const int tid = threadIdx.x;
    const int warp = tid >> 5, lane = tid & 31;
    const int qr = lane >> 2, qc = lane & 3;
    const int half = warp & 1;
    const int wrow = (warp >> 1) * 32;
    const int lt15 = lane & 15, lt7 = lane & 7;
    const int asel = lane >> 4;
    const int brow = lane >> 4;
    const int bsel = (lane >> 3) & 1;

    const size_t qkbase = (size_t)(b*HH + h) * SS * 64;
    const size_t vbase  = (size_t)(b*HH + h) * DH * (SS/2);
    const float scale = 0.08838834764831845f;

    // ---- prologue: Q (128 rows) + K_0 ----
    #pragma unroll
    for (int rep = 0; rep < 8; rep++) {
        const int idx = rep*256 + tid;
        const int r = idx >> 4, g = idx & 15;
        const int dst = r*64 + ((g ^ (r & 7)) << 2);
        const size_t qsrc = qkbase + (size_t)(qm0 + r)*64 + g*4;
        cpasync16u(smu + AQH + dst, g_qh + qsrc);
        cpasync16u(smu + AQL + dst, g_ql + qsrc);
    }
    #pragma unroll
    for (int rep = 0; rep < 4; rep++) {
        const int idx = rep*256 + tid;
        const int r = idx >> 4, g = idx & 15;
        const int dst = r*64 + ((g ^ (r & 7)) << 2);
        const size_t ksrc = qkbase + (size_t)r*64 + g*4;
        cpasync16u(smu + AKH + dst, g_kh + ksrc);
        cpasync16u(smu + AKL + dst, g_kl + ksrc);
    }
    asm volatile("cp.async.commit_group;\n");
    asm volatile("cp.async.wait_group 0;\n");
    __syncthreads();

    float ls[2][2];
    ls[0][0] = ls[0][1] = ls[1][0] = ls[1][1] = 0.f;
    float O[16][4];
    #pragma unroll
    for (int n = 0; n < 16; n++)
        #pragma unroll
        for (int u = 0; u < 4; u++) O[n][u] = 0.f;

    const int nt = 2*qb + 2;

    for (int t = 0; t < nt; t++) {
        const int kn0 = t * 64;
        if (t > 0) __syncthreads();    // PV t-1 done: V/P/K buffers free

        // ---- issue V_t ----
        #pragma unroll
        for (int rep = 0; rep < 4; rep++) {
            const int idx = rep*256 + tid;
            const int d = idx >> 3, g = idx & 7;
            const int dst = d*32 + ((g ^ (d & 7)) << 2);
            const size_t src = vbase + (size_t)d*(SS/2) + (kn0 >> 1) + g*4;
            cpasync16u(smu + AVH + dst, g_vf + src);
        }
        asm volatile("cp.async.commit_group;\n");

        asm volatile("cp.async.wait_group 1;\n");   // K_t ready
        __syncthreads();

        // ---- S = Q K^T (bf16 3-product): 2 im x 4 nf frags ----
        float Sf[2][4][4];
        #pragma unroll
        for (int im = 0; im < 2; im++)
            #pragma unroll
            for (int n = 0; n < 4; n++)
                #pragma unroll
                for (int u = 0; u < 4; u++) Sf[im][n][u] = 0.f;

        #pragma unroll
        for (int ch = 0; ch < 8; ch++) {
            uint32_t ah[2][4], al[2][4];
            #pragma unroll
            for (int im = 0; im < 2; im++) {
                const int row = wrow + im*16 + lt15;
                const int gr = 2*ch + asel;
                const uint32_t off = 4*(row*64 + ((gr ^ (row & 7)) << 2));
                ldm_x4(ah[im], sb + AQH*4 + off);
                ldm_x4(al[im], sb + AQL*4 + off);
            }
            uint32_t kh[2][4], kl[2][4];
            #pragma unroll
            for (int ip = 0; ip < 2; ip++) {
                const int kr = (half*4 + ip*2 + brow)*8 + lt7;
                const int gr = 2*ch + bsel;
                const uint32_t off = 4*(kr*64 + ((gr ^ (kr & 7)) << 2));
                ldm_x4(kh[ip], sb + AKH*4 + off);
                ldm_x4(kl[ip], sb + AKL*4 + off);
            }
            #pragma unroll
            for (int nf = 0; nf < 4; nf++) {
                uint32_t bh[2] = { kh[nf>>1][(nf&1)*2], kh[nf>>1][(nf&1)*2 + 1] };
                uint32_t bl[2] = { kl[nf>>1][(nf&1)*2], kl[nf>>1][(nf&1)*2 + 1] };
                #pragma unroll
                for (int im = 0; im < 2; im++) {
                    mma_bf16(Sf[im][nf], ah[im], bh);
                    mma_bf16(Sf[im][nf], al[im], bh);
                    mma_bf16(Sf[im][nf], ah[im], bl);
                }
            }
        }

        // ---- exp + P store (diagonal spans last TWO tiles) ----
        const bool maskt = (t >= nt - 2);
        #pragma unroll
        for (int im = 0; im < 2; im++) {
            const int row0 = qm0 + wrow + im*16 + qr, row1 = row0 + 8;
            #pragma unroll
            for (int nf = 0; nf < 4; nf++) {
                const int key0 = kn0 + (half*4 + nf)*8 + 2*qc;
                float p00 = __expf(fmaf(Sf[im][nf][0], scale, -SHIFTC));
                float p01 = __expf(fmaf(Sf[im][nf][1], scale, -SHIFTC));
                float p10 = __expf(fmaf(Sf[im][nf][2], scale, -SHIFTC));
                float p11 = __expf(fmaf(Sf[im][nf][3], scale, -SHIFTC));
                if (maskt) {
                    if (key0     > row0) p00 = 0.f;
                    if (key0 + 1 > row0) p01 = 0.f;
                    if (key0     > row1) p10 = 0.f;
                    if (key0 + 1 > row1) p11 = 0.f;
                }
                ls[im][0] += p00 + p01;
                ls[im][1] += p10 + p11;
                const int pp = (half*4 + nf)*4 + qc;
                smu[APH + xsw(wrow + im*16 + qr, pp, 32)]     = packf16(p00, p01);
                smu[APH + xsw(wrow + im*16 + qr + 8, pp, 32)] = packf16(p10, p11);
            }
        }

        asm volatile("cp.async.wait_group 0;\n");   // V_t ready
        __syncthreads();                            // P visible

        // ---- issue K_{t+1} ----
        if (t + 1 < nt) {
            #pragma unroll
            for (int rep = 0; rep < 4; rep++) {
                const int idx = rep*256 + tid;
                const int r = idx >> 4, g = idx & 15;
                const int dst = r*64 + ((g ^ (r & 7)) << 2);
                const size_t src = qkbase + (size_t)(kn0 + 64 + r)*64 + g*4;
                cpasync16u(smu + AKH + dst, g_kh + src);
                cpasync16u(smu + AKL + dst, g_kl + src);
            }
            asm volatile("cp.async.commit_group;\n");
        }

        // ---- O += P V (fp16, ldmatrix): 2 im x 8 nf ----
        #pragma unroll
        for (int ch = 0; ch < 4; ch++) {
            uint32_t ap[2][4];
            #pragma unroll
            for (int im = 0; im < 2; im++) {
                const int row = wrow + im*16 + lt15;
                const int gr = 2*ch + asel;
                ldm_x4(ap[im], sb + APH*4 + 4*(row*32 + ((gr ^ (row & 7)) << 2)));
            }
            uint32_t vv[4][4];
            #pragma unroll
            for (int ip = 0; ip < 4; ip++) {
                const int dr = (half*8 + ip*2 + brow)*8 + lt7;
                const int gr = 2*ch + bsel;
                ldm_x4(vv[ip], sb + AVH*4 + 4*(dr*32 + ((gr ^ (dr & 7)) << 2)));
            }
            #pragma unroll
            for (int nf = 0; nf < 8; nf++) {
                uint32_t bb[2] = { vv[nf>>1][(nf&1)*2], vv[nf>>1][(nf&1)*2 + 1] };
                #pragma unroll
                for (int im = 0; im < 2; im++)
                    mma_f16(O[im*8 + nf], ap[im], bb);
            }
        }
    }

    // ---- epilogue: reduce l across quads + halves, write O/l ----
    #pragma unroll
    for (int im = 0; im < 2; im++)
        #pragma unroll
        for (int rr = 0; rr < 2; rr++) {
            float v = ls[im][rr];
            v += __shfl_xor_sync(0xffffffffu, v, 1);
            v += __shfl_xor_sync(0xffffffffu, v, 2);
            ls[im][rr] = v;
        }
    __syncthreads();
    if (qc == 0) {
        #pragma unroll
        for (int im = 0; im < 2; im++) {
            smf[ALRED + half*128 + wrow + im*16 + qr]     = ls[im][0];
            smf[ALRED + half*128 + wrow + im*16 + qr + 8] = ls[im][1];
        }
    }
    __syncthreads();

    #pragma unroll
    for (int im = 0; im < 2; im++) {
        const int rl0 = wrow + im*16 + qr;
        const float il0 = 1.0f / (smf[ALRED + rl0] + smf[ALRED + 128 + rl0]);
        const float il1 = 1.0f / (smf[ALRED + rl0 + 8] + smf[ALRED + 128 + rl0 + 8]);
        const size_t gr0 = (size_t)(b*SS + qm0 + rl0);
        #pragma unroll
        for (int nf = 0; nf < 8; nf++) {
            const int col = h*DH + (half*8 + nf)*8 + 2*qc;
            *(float2*)(g_attn + gr0 * DD + col) =
                make_float2(O[im*8+nf][0]*il0, O[im*8+nf][1]*il0);
            *(float2*)(g_attn + (gr0 + 8) * DD + col) =
                make_float2(O[im*8+nf][2]*il1, O[im*8+nf][3]*il1);
        }
    }
}

// ---------------------------------------------------------------------------
// RMSNorm over D=2048 + pack to fp16 plane. One block per row.
// ---------------------------------------------------------------------------
__global__ __launch_bounds__(256) void rmsnorm_pack_rows(const float* __restrict__ w)
{
    __shared__ float red[8];
    __shared__ float s_inv;
    const float* p = g_attn + (size_t)blockIdx.x * DD;
    const int tid = threadIdx.x;
    const int base = tid * 8;

    float v[8];
    {
        const float4 a = *(const float4*)(p + base);
        const float4 b = *(const float4*)(p + base + 4);
        v[0]=a.x; v[1]=a.y; v[2]=a.z; v[3]=a.w;
        v[4]=b.x; v[5]=b.y; v[6]=b.z; v[7]=b.w;
    }
    float ss = 0.f;
    #pragma unroll
    for (int k = 0; k < 8; k++) ss += v[k]*v[k];
    #pragma unroll
    for (int o = 16; o > 0; o >>= 1) ss += __shfl_xor_sync(0xffffffffu, ss, o);
    if ((tid & 31) == 0) red[tid >> 5] = ss;
    __syncthreads();
    if (tid == 0) {
        float t = 0.f;
        #pragma unroll
        for (int i = 0; i < 8; i++) t += red[i];
        s_inv = rsqrtf(t * (1.0f / DD) + EPS);
    }
    __syncthreads();
    const float inv = s_inv;
    const size_t ob = (size_t)blockIdx.x * (DD/2) + base/2;
    #pragma unroll
    for (int u = 0; u < 4; u++) {
        const float x0 = v[2*u]   * inv * w[base + 2*u];
        const float x1 = v[2*u+1] * inv * w[base + 2*u + 1];
        g_af[ob + u] = packf16(x0, x1);
    }
}

// ---------------------------------------------------------------------------
extern "C" void kernel_launch(void* const* d_in, const int* in_sizes, int n_in,
                              void* d_out, int out_size)
{
    const float* x     = (const float*)d_in[0];
    const float* rp    = (const float*)d_in[1];
    const float* Win   = (const float*)d_in[2];
    const float* b_in  = (const float*)d_in[3];
    const float* Wout  = (const float*)d_in[4];
    const float* b_out = (const float*)d_in[5];
    const float* qk_w  = (const float*)d_in[6];
    const float* out_w = (const float*)d_in[7];
    float* out = (float*)d_out;

    uint32_t *xf, *wif, *wof, *af;
    cudaGetSymbolAddress((void**)&xf,  g_xf);
    cudaGetSymbolAddress((void**)&wif, g_wif);
    cudaGetSymbolAddress((void**)&wof, g_wof);
    cudaGetSymbolAddress((void**)&af,  g_af);

    const int gemm_smem = 2 * GBUF * (int)sizeof(uint32_t);   // 65536 B
    cudaFuncSetAttribute(f16_gemm_qkv_fused,
                         cudaFuncAttributeMaxDynamicSharedMemorySize, gemm_smem);
    cudaFuncSetAttribute(f16_gemm_nt_bias,
                         cudaFuncAttributeMaxDynamicSharedMemorySize, gemm_smem);
    cudaFuncSetAttribute(flash_attn_v5,
                         cudaFuncAttributeMaxDynamicSharedMemorySize, ASZ);

    // 0) rope tables + fp16 planes
    rope_tab<<<(SS*64)/256, 256>>>(rp);
    split_plane_f16<<<(MM*DD)/1024, 256>>>(x, xf);
    split_plane_f16<<<(TRIO*DD)/1024, 256>>>(Win, wif);
    split_plane_f16<<<(DD*DD)/1024, 256>>>(Wout, wof);

    // 1) fused QKV GEMM + rope/rms/split epilogue
    {
        dim3 grid(TRIO / 128, MM / 128);
        f16_gemm_qkv_fused<<<grid, 256, gemm_smem>>>(xf, wif, b_in, qk_w);
    }
    // 2) flash attention -> g_attn
    {
        dim3 grid(SS / 128, HH, BB);
        flash_attn_v5<<<grid, 256, ASZ>>>();
    }
    // 3) RMSNorm + pack -> g_af
    rmsnorm_pack_rows<<<MM, 256>>>(out_w);
    // 4) out = attn @ Wout^T + b_out
    {
        dim3 grid(DD / 128, MM / 128);
        f16_gemm_nt_bias<<<grid, 256, gemm_smem>>>(
            af, wof, b_out, out, MM, DD, DD/2);
    }
}